// round 17
// baseline (speedup 1.0000x reference)
#include <cuda_runtime.h>
#include <cuda_fp16.h>
#include <math.h>
#include <stdint.h>

#define NMAX 100096
#define EMAX 3200000
#define HDIM 128
#define NGRAPH 64
#define NBLK 128   // max scan blocks (ceil(NMAX/1024))

// ---------------- scratch (static __device__, no allocation) ----------------
__device__ __half g_u[(size_t)NMAX * HDIM];  // u = x @ W (fp16, unscaled)
__device__ __half g_h[(size_t)NMAX * HDIM];  // layer output (fp16)
__device__ float  g_dinv[NMAX];
__device__ int    g_counts[NMAX];
__device__ int    g_cursor[NMAX];
__device__ int    g_rowptr[NMAX + 1];
__device__ int    g_esrc[EMAX];
__device__ float  g_pool[NGRAPH * HDIM];
__device__ int    g_bsum[NBLK];
__device__ int    g_boff[NBLK];

// ---------------- helpers ----------------
__device__ __forceinline__ void mma_fp16(float* c, const uint32_t* a, const uint32_t* b) {
    asm("mma.sync.aligned.m16n8k16.row.col.f32.f16.f16.f32 "
        "{%0,%1,%2,%3}, {%4,%5,%6,%7}, {%8,%9}, {%0,%1,%2,%3};"
        : "+f"(c[0]), "+f"(c[1]), "+f"(c[2]), "+f"(c[3])
        : "r"(a[0]), "r"(a[1]), "r"(a[2]), "r"(a[3]), "r"(b[0]), "r"(b[1]));
}
// load 8 consecutive A elems -> 4 half2 regs (fp32 / fp16 source overloads)
__device__ __forceinline__ void loadA8(const float* p, uint32_t* d) {
    float4 a = __ldcs((const float4*)p);
    float4 b = __ldcs((const float4*)(p + 4));
    __half2 h0 = __floats2half2_rn(a.x, a.y);
    __half2 h1 = __floats2half2_rn(a.z, a.w);
    __half2 h2 = __floats2half2_rn(b.x, b.y);
    __half2 h3 = __floats2half2_rn(b.z, b.w);
    d[0] = *(uint32_t*)&h0; d[1] = *(uint32_t*)&h1;
    d[2] = *(uint32_t*)&h2; d[3] = *(uint32_t*)&h3;
}
__device__ __forceinline__ void loadA8(const __half* p, uint32_t* d) {
    uint4 v = __ldcs((const uint4*)p);
    d[0] = v.x; d[1] = v.y; d[2] = v.z; d[3] = v.w;
}
// acc[0..7] += d * (8 fp16 of w)
__device__ __forceinline__ void acc8(float* acc, uint4 w, float d) {
    float2 f0 = __half22float2(*(__half2*)&w.x);
    float2 f1 = __half22float2(*(__half2*)&w.y);
    float2 f2 = __half22float2(*(__half2*)&w.z);
    float2 f3 = __half22float2(*(__half2*)&w.w);
    acc[0] = fmaf(d, f0.x, acc[0]); acc[1] = fmaf(d, f0.y, acc[1]);
    acc[2] = fmaf(d, f1.x, acc[2]); acc[3] = fmaf(d, f1.y, acc[3]);
    acc[4] = fmaf(d, f2.x, acc[4]); acc[5] = fmaf(d, f2.y, acc[5]);
    acc[6] = fmaf(d, f3.x, acc[6]); acc[7] = fmaf(d, f3.y, acc[7]);
}

// ---------------- zero scratch ----------------
__global__ void zero_kernel(int n) {
    int i = blockIdx.x * blockDim.x + threadIdx.x;
    if (i < n) g_counts[i] = 0;
    if (i < NGRAPH * HDIM) g_pool[i] = 0.0f;
}

// ---------------- in-degree histogram over dst ----------------
__global__ void hist_kernel(const int* __restrict__ dst, int E) {
    int e = blockIdx.x * blockDim.x + threadIdx.x;
    if (e < E) atomicAdd(&g_counts[__ldcs(dst + e)], 1);
}

// ---------------- scan phase 1: per-block (1024 elems) sums, coalesced ------
__global__ void scan1_kernel(int n) {
    int b = blockIdx.x, t = threadIdx.x;
    int base = b * 1024 + t * 4;
    int s = 0;
    if (base + 3 < n) {
        int4 c = *(const int4*)&g_counts[base];
        s = c.x + c.y + c.z + c.w;
    } else {
        for (int j = 0; j < 4; j++) if (base + j < n) s += g_counts[base + j];
    }
#pragma unroll
    for (int d = 16; d > 0; d >>= 1) s += __shfl_down_sync(0xffffffffu, s, d);
    __shared__ int ws[8];
    if ((t & 31) == 0) ws[t >> 5] = s;
    __syncthreads();
    if (t == 0) {
        int tot = 0;
#pragma unroll
        for (int w = 0; w < 8; w++) tot += ws[w];
        g_bsum[b] = tot;
    }
}

// ---------------- scan phase 2: scan block sums (nb <= 128) -----------------
__global__ void scan2_kernel(int nb, int n) {
    int t = threadIdx.x;  // 128 threads
    int v = (t < nb) ? g_bsum[t] : 0;
    int incl = v;
#pragma unroll
    for (int d = 1; d < 32; d <<= 1) {
        int o = __shfl_up_sync(0xffffffffu, incl, d);
        if ((t & 31) >= d) incl += o;
    }
    __shared__ int ws[4];
    if ((t & 31) == 31) ws[t >> 5] = incl;
    __syncthreads();
    int woff = 0;
#pragma unroll
    for (int w = 0; w < 4; w++) if (w < (t >> 5)) woff += ws[w];
    incl += woff;
    if (t < nb) g_boff[t] = incl - v;   // exclusive
    if (t == 127) g_rowptr[n] = incl;   // total
}

// ---------------- scan phase 3: local prefix + offset; rowptr/cursor/dinv ---
__global__ void scan3_kernel(int n) {
    int b = blockIdx.x, t = threadIdx.x;
    int base = b * 1024 + t * 4;
    int4 c = make_int4(0, 0, 0, 0);
    if (base + 3 < n) {
        c = *(const int4*)&g_counts[base];
    } else {
        if (base + 0 < n) c.x = g_counts[base + 0];
        if (base + 1 < n) c.y = g_counts[base + 1];
        if (base + 2 < n) c.z = g_counts[base + 2];
        if (base + 3 < n) c.w = g_counts[base + 3];
    }
    int s = c.x + c.y + c.z + c.w;
    int incl = s;
#pragma unroll
    for (int d = 1; d < 32; d <<= 1) {
        int o = __shfl_up_sync(0xffffffffu, incl, d);
        if ((t & 31) >= d) incl += o;
    }
    __shared__ int ws[8];
    if ((t & 31) == 31) ws[t >> 5] = incl;
    __syncthreads();
    int woff = 0;
#pragma unroll
    for (int w = 0; w < 8; w++) if (w < (t >> 5)) woff += ws[w];
    int run = g_boff[b] + woff + incl - s;
    if (base + 0 < n) { g_rowptr[base+0]=run; g_cursor[base+0]=run; g_dinv[base+0]=rsqrtf((float)c.x+1.f); run+=c.x; }
    if (base + 1 < n) { g_rowptr[base+1]=run; g_cursor[base+1]=run; g_dinv[base+1]=rsqrtf((float)c.y+1.f); run+=c.y; }
    if (base + 2 < n) { g_rowptr[base+2]=run; g_cursor[base+2]=run; g_dinv[base+2]=rsqrtf((float)c.z+1.f); run+=c.z; }
    if (base + 3 < n) { g_rowptr[base+3]=run; g_cursor[base+3]=run; g_dinv[base+3]=rsqrtf((float)c.w+1.f); }
}

// ---------------- fill CSR with src ids (cursor pre-seeded to rowptr) -------
__global__ void fill_kernel(const int* __restrict__ src,
                            const int* __restrict__ dst, int E) {
    int e = blockIdx.x * blockDim.x + threadIdx.x;
    if (e < E) {
        int d = __ldcs(dst + e);
        int pos = atomicAdd(&g_cursor[d], 1);
        g_esrc[pos] = __ldcs(src + e);
    }
}

// ---------------- fp16 tensor-core GEMM (m16n8k16, fp32 accum) --------------
template<typename T>
__global__ __launch_bounds__(256, 2) void sgemm_fp16(
    const T* __restrict__ A, const float* __restrict__ B,
    __half* __restrict__ U, int N, int K)
{
    __shared__ uint32_t As2[2][128][12];   // [row][k/2] half2
    __shared__ uint32_t Bs2[2][128][12];   // [col][k/2] half2 (transposed)

    int tid = threadIdx.x;
    int wid = tid >> 5, lane = tid & 31;
    int g = lane >> 2, t = lane & 3;
    int warp_m = wid >> 2, warp_n = wid & 3;
    int row0 = blockIdx.x * 128;
    int m0 = warp_m * 64, n0 = warp_n * 32;

    float acc[4][4][4];
#pragma unroll
    for (int mi = 0; mi < 4; mi++)
#pragma unroll
        for (int ni = 0; ni < 4; ni++)
#pragma unroll
            for (int r = 0; r < 4; r++) acc[mi][ni][r] = 0.0f;

    int a_r = tid >> 1;
    int a_h = (tid & 1) * 4;
    int garow = row0 + a_r;
    const T* Arow = A + (size_t)(garow < N ? garow : 0) * K + a_h * 2;

    int b_cg = lane >> 2;   // 0..7
    int b_k2 = lane & 3;    // 0..3

    uint32_t areg[4], breg[4];

    loadA8(Arow, areg);
#pragma unroll
    for (int p = 0; p < 4; p++) {
        int c  = wid * 16 + (p & 1) * 8 + b_cg;
        int k2 = b_k2 + (p >> 1) * 4;
        float lo = __ldg(&B[(size_t)(2 * k2) * HDIM + c]);
        float hi = __ldg(&B[(size_t)(2 * k2 + 1) * HDIM + c]);
        __half2 hh = __floats2half2_rn(lo, hi);
        breg[p] = *(uint32_t*)&hh;
    }
#pragma unroll
    for (int j = 0; j < 4; j++) As2[0][a_r][a_h + j] = areg[j];
#pragma unroll
    for (int p = 0; p < 4; p++) {
        int c  = wid * 16 + (p & 1) * 8 + b_cg;
        int k2 = b_k2 + (p >> 1) * 4;
        Bs2[0][c][k2] = breg[p];
    }
    __syncthreads();

    int buf = 0;
    for (int k0 = 0; k0 < K; k0 += 16) {
        int nk = k0 + 16;
        if (nk < K) {
            loadA8(Arow + nk, areg);
#pragma unroll
            for (int p = 0; p < 4; p++) {
                int c  = wid * 16 + (p & 1) * 8 + b_cg;
                int k2 = b_k2 + (p >> 1) * 4;
                float lo = __ldg(&B[(size_t)(nk + 2 * k2) * HDIM + c]);
                float hi = __ldg(&B[(size_t)(nk + 2 * k2 + 1) * HDIM + c]);
                __half2 hh = __floats2half2_rn(lo, hi);
                breg[p] = *(uint32_t*)&hh;
            }
        }
        uint32_t bf[4][2];
#pragma unroll
        for (int ni = 0; ni < 4; ni++) {
            int col = n0 + ni * 8 + g;
            bf[ni][0] = Bs2[buf][col][t];
            bf[ni][1] = Bs2[buf][col][t + 4];
        }
#pragma unroll
        for (int mi = 0; mi < 4; mi++) {
            int r1 = m0 + mi * 16 + g;
            uint32_t af[4];
            af[0] = As2[buf][r1][t];
            af[1] = As2[buf][r1 + 8][t];
            af[2] = As2[buf][r1][t + 4];
            af[3] = As2[buf][r1 + 8][t + 4];
#pragma unroll
            for (int ni = 0; ni < 4; ni++)
                mma_fp16(acc[mi][ni], af, bf[ni]);
        }
        if (nk < K) {
            int nb = buf ^ 1;
#pragma unroll
            for (int j = 0; j < 4; j++) As2[nb][a_r][a_h + j] = areg[j];
#pragma unroll
            for (int p = 0; p < 4; p++) {
                int c  = wid * 16 + (p & 1) * 8 + b_cg;
                int k2 = b_k2 + (p >> 1) * 4;
                Bs2[nb][c][k2] = breg[p];
            }
        }
        __syncthreads();
        buf ^= 1;
    }

#pragma unroll
    for (int mi = 0; mi < 4; mi++) {
        int r1 = row0 + m0 + mi * 16 + g;
        int r2 = r1 + 8;
#pragma unroll
        for (int ni = 0; ni < 4; ni++) {
            int c = n0 + ni * 8 + 2 * t;
            if (r1 < N) {
                __half2 h = __floats2half2_rn(acc[mi][ni][0], acc[mi][ni][1]);
                __stcs((__half2*)&U[(size_t)r1 * HDIM + c], h);
            }
            if (r2 < N) {
                __half2 h = __floats2half2_rn(acc[mi][ni][2], acc[mi][ni][3]);
                __stcs((__half2*)&U[(size_t)r2 * HDIM + c], h);
            }
        }
    }
}

// ---------------- CSR gather aggregation: 1 warp/row, half-warp/edge --------
// Lanes 0-15 handle edge j, lanes 16-31 edge j+1; each lane loads uint4
// (8 fp16) so one warp LDG.128 covers TWO gathered rows. Cross-half combine
// via shfl_down(16) at the end. Lanes >= nn hold dvl=0 -> zero contribution.
__global__ __launch_bounds__(256) void agg_kernel(
    const __half* __restrict__ Uin, __half* __restrict__ Out,
    const float* __restrict__ bias, int N)
{
    int gwarp = (blockIdx.x * blockDim.x + threadIdx.x) >> 5;
    int lane = threadIdx.x & 31;
    if (gwarp >= N) return;
    int v = gwarp;
    int halfid = lane >> 4;
    int co = (lane & 15) * 8;               // 8 fp16 columns per lane
    const __half* Ucol = Uin + co;

    int beg = g_rowptr[v], end = g_rowptr[v + 1];
    float dv = g_dinv[v];

    float accA[8], accB[8];
#pragma unroll
    for (int i = 0; i < 8; i++) { accA[i] = 0.f; accB[i] = 0.f; }
    // self loop: only half 0 contributes
    {
        uint4 w = *(const uint4*)&Ucol[(size_t)v * HDIM];
        acc8(accA, w, halfid ? 0.f : dv);
    }

    for (int base = beg; base < end; base += 32) {
        int nn = min(32, end - base);
        int sl = 0; float dvl = 0.f;
        if (lane < nn) { sl = __ldcs(&g_esrc[base + lane]); dvl = g_dinv[sl]; }
        int j = 0;
        for (; j + 3 < nn; j += 4) {
            int i0 = j + halfid;            // < nn (safe: dvl=0 beyond)
            int i1 = j + 2 + halfid;
            int s0 = __shfl_sync(0xffffffffu, sl, i0);
            int s1 = __shfl_sync(0xffffffffu, sl, i1);
            float d0 = __shfl_sync(0xffffffffu, dvl, i0);
            float d1 = __shfl_sync(0xffffffffu, dvl, i1);
            uint4 w0 = *(const uint4*)&Ucol[(size_t)s0 * HDIM];
            uint4 w1 = *(const uint4*)&Ucol[(size_t)s1 * HDIM];
            acc8(accA, w0, d0);
            acc8(accB, w1, d1);
        }
        for (; j < nn; j += 2) {
            int i0 = j + halfid;
            int idx = (i0 < 32) ? i0 : 0;
            int s0 = __shfl_sync(0xffffffffu, sl, idx);
            float d0 = __shfl_sync(0xffffffffu, dvl, idx);
            if (i0 >= nn) d0 = 0.f;
            uint4 w0 = *(const uint4*)&Ucol[(size_t)s0 * HDIM];
            acc8(accA, w0, d0);
        }
    }
#pragma unroll
    for (int i = 0; i < 8; i++) accA[i] += accB[i];
    // combine halves: lane i += lane i+16 (same columns)
#pragma unroll
    for (int i = 0; i < 8; i++)
        accA[i] += __shfl_down_sync(0xffffffffu, accA[i], 16);

    if (halfid == 0) {
        float4 b0 = *(const float4*)&bias[co];
        float4 b1 = *(const float4*)&bias[co + 4];
        float o[8];
        o[0] = fmaxf(fmaf(dv, accA[0], b0.x), 0.f);
        o[1] = fmaxf(fmaf(dv, accA[1], b0.y), 0.f);
        o[2] = fmaxf(fmaf(dv, accA[2], b0.z), 0.f);
        o[3] = fmaxf(fmaf(dv, accA[3], b0.w), 0.f);
        o[4] = fmaxf(fmaf(dv, accA[4], b1.x), 0.f);
        o[5] = fmaxf(fmaf(dv, accA[5], b1.y), 0.f);
        o[6] = fmaxf(fmaf(dv, accA[6], b1.z), 0.f);
        o[7] = fmaxf(fmaf(dv, accA[7], b1.w), 0.f);
        uint4 st;
        __half2 h0 = __floats2half2_rn(o[0], o[1]);
        __half2 h1 = __floats2half2_rn(o[2], o[3]);
        __half2 h2 = __floats2half2_rn(o[4], o[5]);
        __half2 h3 = __floats2half2_rn(o[6], o[7]);
        st.x = *(uint32_t*)&h0; st.y = *(uint32_t*)&h1;
        st.z = *(uint32_t*)&h2; st.w = *(uint32_t*)&h3;
        __stcs((uint4*)&Out[(size_t)v * HDIM + co], st);
    }
}

// ---------------- global max pool per graph (fp16 in, batch sorted) ---------
__global__ void pool_kernel(const __half* __restrict__ Hin,
                            const int* __restrict__ batch, int N)
{
    const int NPW = 16;
    int gwarp = (blockIdx.x * blockDim.x + threadIdx.x) >> 5;
    int lane = threadIdx.x & 31;
    int v0 = gwarp * NPW;
    if (v0 >= N) return;
    int vend = min(v0 + NPW, N);

    int cur_b = batch[v0];
    uint2 w = __ldcs((const uint2*)&Hin[(size_t)v0 * HDIM + lane * 4]);
    float2 m0 = __half22float2(*(__half2*)&w.x);
    float2 m1 = __half22float2(*(__half2*)&w.y);
    float4 m = make_float4(m0.x, m0.y, m1.x, m1.y);
    for (int v = v0 + 1; v < vend; v++) {
        int b = batch[v];
        w = __ldcs((const uint2*)&Hin[(size_t)v * HDIM + lane * 4]);
        float2 x0 = __half22float2(*(__half2*)&w.x);
        float2 x1 = __half22float2(*(__half2*)&w.y);
        float4 x = make_float4(x0.x, x0.y, x1.x, x1.y);
        if (b != cur_b) {
            int* p = (int*)&g_pool[cur_b * HDIM + lane * 4];
            atomicMax(p + 0, __float_as_int(m.x));
            atomicMax(p + 1, __float_as_int(m.y));
            atomicMax(p + 2, __float_as_int(m.z));
            atomicMax(p + 3, __float_as_int(m.w));
            m = x; cur_b = b;
        } else {
            m.x = fmaxf(m.x, x.x); m.y = fmaxf(m.y, x.y);
            m.z = fmaxf(m.z, x.z); m.w = fmaxf(m.w, x.w);
        }
    }
    int* p = (int*)&g_pool[cur_b * HDIM + lane * 4];
    atomicMax(p + 0, __float_as_int(m.x));
    atomicMax(p + 1, __float_as_int(m.y));
    atomicMax(p + 2, __float_as_int(m.z));
    atomicMax(p + 3, __float_as_int(m.w));
}

// ---------------- classifier head + log_softmax -----------------------------
__global__ void head_kernel(const float* __restrict__ Wc,
                            const float* __restrict__ bc,
                            float* __restrict__ out)
{
    int gi = threadIdx.x;  // 64 graphs
    float z0 = bc[0], z1 = bc[1];
#pragma unroll 8
    for (int k = 0; k < HDIM; k++) {
        float v = g_pool[gi * HDIM + k];
        z0 = fmaf(v, Wc[k * 2 + 0], z0);
        z1 = fmaf(v, Wc[k * 2 + 1], z1);
    }
    float mx = fmaxf(z0, z1);
    float lse = mx + logf(expf(z0 - mx) + expf(z1 - mx));
    out[gi * 2 + 0] = z0 - lse;
    out[gi * 2 + 1] = z1 - lse;
}

// ---------------- launch ----------------------------------------------------
extern "C" void kernel_launch(void* const* d_in, const int* in_sizes, int n_in,
                              void* d_out, int out_size)
{
    const float* x     = (const float*)d_in[0];
    const int* eidx    = (const int*)d_in[1];    // int32
    const int* batch   = (const int*)d_in[2];    // int32
    const float* W1 = (const float*)d_in[3];
    const float* b1 = (const float*)d_in[4];
    const float* W2 = (const float*)d_in[5];
    const float* b2 = (const float*)d_in[6];
    const float* Wc = (const float*)d_in[7];
    const float* bc = (const float*)d_in[8];
    float* out = (float*)d_out;

    const int F = 512;
    int N = in_sizes[0] / F;
    int E = in_sizes[1] / 2;
    const int* src = eidx;
    const int* dst = eidx + E;

    __half* u; __half* h;
    cudaGetSymbolAddress((void**)&u, g_u);
    cudaGetSymbolAddress((void**)&h, g_h);

    int gemm_blocks = (N + 127) / 128;
    int agg_blocks  = (N + 7) / 8;          // 1 warp per row
    int pool_warps  = (N + 15) / 16;
    int pool_blocks = (pool_warps * 32 + 255) / 256;
    int scan_blocks = (N + 1023) / 1024;

    // Fork a side stream for the CSR build; GEMM1 (graph-independent)
    // runs concurrently on the capture (default) stream.
    cudaStream_t sb;
    cudaEvent_t evF, evJ;
    cudaStreamCreate(&sb);
    cudaEventCreate(&evF);
    cudaEventCreate(&evJ);

    cudaEventRecord(evF, 0);
    cudaStreamWaitEvent(sb, evF, 0);

    // default stream: GEMM1 (launch 0)
    sgemm_fp16<float><<<gemm_blocks, 256>>>(x, W1, u, N, 512);
    // side stream: coalesced CSR build
    zero_kernel<<<(N + 255) / 256, 256, 0, sb>>>(N);
    hist_kernel<<<(E + 255) / 256, 256, 0, sb>>>(dst, E);
    scan1_kernel<<<scan_blocks, 256, 0, sb>>>(N);     // capture slot (idx 3)
    scan2_kernel<<<1, 128, 0, sb>>>(scan_blocks, N);
    scan3_kernel<<<scan_blocks, 256, 0, sb>>>(N);
    fill_kernel<<<(E + 255) / 256, 256, 0, sb>>>(src, dst, E);
    cudaEventRecord(evJ, sb);
    cudaStreamWaitEvent(0, evJ, 0);                   // join

    agg_kernel<<<agg_blocks, 256>>>(u, h, b1, N);
    sgemm_fp16<__half><<<gemm_blocks, 256>>>(h, W2, u, N, 128);
    agg_kernel<<<agg_blocks, 256>>>(u, h, b2, N);
    pool_kernel<<<pool_blocks, 256>>>(h, batch, N);
    head_kernel<<<1, 64>>>(Wc, bc, out);
}